// round 10
// baseline (speedup 1.0000x reference)
#include <cuda_runtime.h>
#include <cstdint>
#include <cstddef>

// Problem constants
#define BSZ 256      // batch
#define TT  512      // time steps
#define EE  256      // input dim
#define HH  256      // hidden dim
#define NB  4        // batches per cluster

// h buffer geometry: [2][NB][2 halves][HPITCH].
// HPITCH=132: the two K-half broadcast-read streams sit 4 banks apart
// (528B) and stay disjoint as both advance 16B/iter.
#define HPITCH 132
#define BST    (2 * HPITCH)          // batch stride (floats)
#define PST    (NB * BST)            // ping-pong buffer stride (floats)

typedef unsigned long long ull;

// ---- packed f32x2 helpers (Blackwell) -------------------------------------
__device__ __forceinline__ ull fma2(ull a, ull b, ull c) {
    ull d;
    asm("fma.rn.f32x2 %0, %1, %2, %3;" : "=l"(d) : "l"(a), "l"(b), "l"(c));
    return d;
}
__device__ __forceinline__ ull splat2(float x) {
    ull d;
    asm("mov.b64 %0, {%1, %1};" : "=l"(d) : "f"(x));
    return d;
}
__device__ __forceinline__ float2 unpack2(ull a) {
    float2 r;
    asm("mov.b64 {%0, %1}, %2;" : "=f"(r.x), "=f"(r.y) : "l"(a));
    return r;
}
__device__ __forceinline__ uint32_t smem_u32(const void* p) {
    uint32_t a;
    asm("{ .reg .u64 t; cvta.to.shared.u64 t, %1; cvt.u32.u64 %0, t; }"
        : "=r"(a) : "l"(p));
    return a;
}
// fast tanh via MUFU exp: (e^{2z}-1)/(e^{2z}+1)
__device__ __forceinline__ float ftanh(float z) {
    float e = __expf(2.0f * z);
    return __fdividef(e - 1.0f, e + 1.0f);
}

// ---------------------------------------------------------------------------
// Phase 1: gates = sigmoid(X @ Wx^T + b)  via packed-f32x2 SGEMM. (unchanged)
// ---------------------------------------------------------------------------
__global__ __launch_bounds__(256, 2) void gates_kernel(
    const float* __restrict__ X, const float* __restrict__ W,
    const float* __restrict__ bias, float* __restrict__ G)
{
    __shared__ __align__(16) float As[16][128];
    __shared__ __align__(16) float Ws[16][128];

    const int tid = threadIdx.x;
    const int bm = blockIdx.x * 128;
    const int bn = blockIdx.y * 128;
    const int tx = tid & 15;
    const int ty = tid >> 4;
    const int lr = tid >> 2;
    const int lc = (tid & 3) << 2;

    ull acc[8][4];
#pragma unroll
    for (int i = 0; i < 8; ++i)
#pragma unroll
        for (int jj = 0; jj < 4; ++jj) acc[i][jj] = 0ull;

    const float* Xp0 = X + (size_t)(bm + lr) * EE + lc;
    const float* Xp1 = X + (size_t)(bm + lr + 64) * EE + lc;
    const float* Wp0 = W + (size_t)(bn + lr) * EE + lc;
    const float* Wp1 = W + (size_t)(bn + lr + 64) * EE + lc;

    float4 pa0 = *(const float4*)(Xp0);
    float4 pa1 = *(const float4*)(Xp1);
    float4 pw0 = *(const float4*)(Wp0);
    float4 pw1 = *(const float4*)(Wp1);

#pragma unroll 1
    for (int k0 = 0; k0 < EE; k0 += 16) {
        __syncthreads();
        As[lc + 0][lr] = pa0.x; As[lc + 1][lr] = pa0.y;
        As[lc + 2][lr] = pa0.z; As[lc + 3][lr] = pa0.w;
        As[lc + 0][lr + 64] = pa1.x; As[lc + 1][lr + 64] = pa1.y;
        As[lc + 2][lr + 64] = pa1.z; As[lc + 3][lr + 64] = pa1.w;
        Ws[lc + 0][lr] = pw0.x; Ws[lc + 1][lr] = pw0.y;
        Ws[lc + 2][lr] = pw0.z; Ws[lc + 3][lr] = pw0.w;
        Ws[lc + 0][lr + 64] = pw1.x; Ws[lc + 1][lr + 64] = pw1.y;
        Ws[lc + 2][lr + 64] = pw1.z; Ws[lc + 3][lr + 64] = pw1.w;
        __syncthreads();

        if (k0 + 16 < EE) {
            pa0 = *(const float4*)(Xp0 + k0 + 16);
            pa1 = *(const float4*)(Xp1 + k0 + 16);
            pw0 = *(const float4*)(Wp0 + k0 + 16);
            pw1 = *(const float4*)(Wp1 + k0 + 16);
        }

#pragma unroll
        for (int k = 0; k < 16; ++k) {
            float a[8];
            *(float4*)&a[0] = *(const float4*)&As[k][ty * 8];
            *(float4*)&a[4] = *(const float4*)&As[k][ty * 8 + 4];
            ulonglong2 u0 = *(const ulonglong2*)&Ws[k][tx * 8];
            ulonglong2 u1 = *(const ulonglong2*)&Ws[k][tx * 8 + 4];
            const ull b0 = u0.x, b1 = u0.y, b2 = u1.x, b3 = u1.y;
#pragma unroll
            for (int i = 0; i < 8; ++i) {
                const ull s = splat2(a[i]);
                acc[i][0] = fma2(s, b0, acc[i][0]);
                acc[i][1] = fma2(s, b1, acc[i][1]);
                acc[i][2] = fma2(s, b2, acc[i][2]);
                acc[i][3] = fma2(s, b3, acc[i][3]);
            }
        }
    }

    float bb[8];
#pragma unroll
    for (int jj = 0; jj < 8; ++jj) bb[jj] = bias[bn + tx * 8 + jj];

#pragma unroll
    for (int i = 0; i < 8; ++i) {
        const size_t m = bm + ty * 8 + i;
        float v[8];
#pragma unroll
        for (int jj = 0; jj < 4; ++jj) {
            float2 z = unpack2(acc[i][jj]);
            float z0 = z.x + bb[2 * jj];
            float z1 = z.y + bb[2 * jj + 1];
            v[2 * jj]     = 1.0f / (1.0f + __expf(-z0));
            v[2 * jj + 1] = 1.0f / (1.0f + __expf(-z1));
        }
        float4 o0 = {v[0], v[1], v[2], v[3]};
        float4 o1 = {v[4], v[5], v[6], v[7]};
        *(float4*)(G + m * HH + bn + tx * 8)     = o0;
        *(float4*)(G + m * HH + bn + tx * 8 + 4) = o1;
    }
}

// ---------------------------------------------------------------------------
// Phase 2: MGU recurrence — partial-wait skeleton + shfl reduce + role stores.
//   Cluster(2) x 64, NB=4 batches, 512 steps. CTA rank r owns rows
//   [r*128, r*128+128). 256 threads: pair layout j = tid>>1, kh = tid&1.
//   Thread holds W[jg][kh*128..+128) in 64 packed regs; 4 batch accumulators.
//
//   Per step:
//     gate prefetch
//     -> ONLY lanes with kh != rank (peer-data consumers) poll mb[p]
//        (lanes kh == rank read locally-written h: __syncthreads of step
//         t-1 already orders it; they start the matvec immediately)
//     -> matvec (32 iters) -> shfl_xor(1) pair reduce -> update own 2 streams
//     -> shfl_xor(1) x2 to exchange h pairs (each lane now has all 4 batch
//        values for row j)
//     -> lane kh==rank:   4x STS  into local buffer q  (WAR: end-of-step BAR)
//        lane kh==rank^1: 4x st.cluster into peer buffer q — THIS lane waited
//        on mb[p], whose arrivals were posted by peer AFTER its t-1 matvec
//        reads => peer-store WAR is provably closed (R5 had this race open)
//     -> __syncwarp -> lane (rank^1): arrive.release.cluster on PEER mb[q]
//        (8 warp-aggregated arrivals; mb count = 8)
//     -> STG out -> __syncthreads (local WAR + loose lockstep).
//   Lap-safety: peer's phase-N+1 arrivals require my N+1 arrivals, which
//   require my wait on that same barrier at phase N.
// ---------------------------------------------------------------------------
__global__ void __cluster_dims__(2, 1, 1) __launch_bounds__(256, 1)
mgu_scan(const float* __restrict__ Whw, const float* __restrict__ Whb,
         float* out)
{
    __shared__ __align__(16) float hsh[2 * PST];   // [p][b][half][HPITCH]
    __shared__ __align__(8)  ull  bars[2];

    const int tid = threadIdx.x;
    const int j   = tid >> 1;       // row within CTA half (0..127)
    const int kh  = tid & 1;        // K half (0..1)
    uint32_t rank;
    asm("mov.u32 %0, %%cluster_ctarank;" : "=r"(rank));
    const int jg = (int)rank * 128 + j;
    const int bbase = (blockIdx.x >> 1) * NB;
    const int b0 = 2 * kh;          // this lane finalizes batches b0, b0+1
    const bool is_waiter = (kh != (int)rank);   // consumes peer-written half

    // --- W row half (128 floats) into 64 packed registers ---
    ull wv[64];
    {
        const ulonglong2* wp =
            (const ulonglong2*)(Whw + (size_t)jg * HH + kh * 128);
#pragma unroll
        for (int i = 0; i < 32; ++i) {
            ulonglong2 v = wp[i];
            wv[2 * i] = v.x; wv[2 * i + 1] = v.y;
        }
    }

    for (int i = tid; i < 2 * PST; i += 256) hsh[i] = 0.0f;

    if (tid == 0) {
        asm volatile("mbarrier.init.shared.b64 [%0], 8;"
                     :: "r"(smem_u32(&bars[0])) : "memory");
        asm volatile("mbarrier.init.shared.b64 [%0], 8;"
                     :: "r"(smem_u32(&bars[1])) : "memory");
    }

    const float biasr = Whb[jg];

    // out pointers for the 2 owned (batch,row) streams
    float* po0 = out + (size_t)(bbase + b0) * TT * HH + jg;
    float* po1 = po0 + (size_t)TT * HH;

    float gc0 = po0[0], gc1 = po1[0];   // gates t=0
    float hc0 = 0.0f, hc1 = 0.0f;       // persistent h for owned streams

    // cluster addresses
    const uint32_t hl  = smem_u32(hsh);
    const uint32_t bl0 = smem_u32(&bars[0]);
    uint32_t hr, br0;
    asm("mapa.shared::cluster.u32 %0, %1, %2;"
        : "=r"(hr) : "r"(hl), "r"(rank ^ 1u));
    asm("mapa.shared::cluster.u32 %0, %1, %2;"
        : "=r"(br0) : "r"(bl0), "r"(rank ^ 1u));

    // Store offsets (floats) within a buffer for row jg, all 4 batches:
    // off(b) = b*BST + rank*HPITCH + j
    const int row_off = (int)rank * HPITCH + j;
    // remote-arrive designated lane: lane index rank^1 has kh = rank^1
    const bool arr_lane = ((tid & 31) == (int)(rank ^ 1u));

    __syncthreads();
    // one-time: both CTAs' smem + mbarrier init visible cluster-wide
    asm volatile("barrier.cluster.arrive.aligned;" ::: "memory");
    asm volatile("barrier.cluster.wait.aligned;"   ::: "memory");

    uint32_t ph0 = 0, ph1 = 0;

#pragma unroll 1
    for (int t = 0; t < TT; ++t) {
        const int p = t & 1;
        const int q = p ^ 1;
        const bool not_last = (t + 1 < TT);

        // prefetch gates for t+1 (issued before any waiting)
        float gn0 = 0.f, gn1 = 0.f;
        if (not_last) {
            const size_t o = (size_t)(t + 1) * HH;
            gn0 = po0[o]; gn1 = po1[o];
        }

        // partial wait: only peer-data consumers poll for the 8 peer arrivals
        if (t > 0 && is_waiter) {
            const uint32_t mb = bl0 + (uint32_t)p * 8u;
            const uint32_t par = p ? ph1 : ph0;
            uint32_t done;
            do {
                asm volatile(
                    "{\n\t.reg .pred P;\n\t"
                    "mbarrier.try_wait.parity.acquire.cluster.shared::cta.b64 "
                    "P, [%1], %2, 0x989680;\n\t"
                    "selp.b32 %0, 1, 0, P;\n\t}"
                    : "=r"(done) : "r"(mb), "r"(par) : "memory");
            } while (!done);
        }
        if (t > 0) { if (p) ph1 ^= 1; else ph0 ^= 1; }

        // ---- matvec over this thread's K-half (128 elems = 32 x 4), 4 b ----
        const float* hb = hsh + p * PST + kh * HPITCH;
        const ulonglong2* x0 = (const ulonglong2*)(hb);
        const ulonglong2* x1 = (const ulonglong2*)(hb + BST);
        const ulonglong2* x2 = (const ulonglong2*)(hb + 2 * BST);
        const ulonglong2* x3 = (const ulonglong2*)(hb + 3 * BST);
        ull a0 = 0, a1 = 0, a2 = 0, a3 = 0;
#pragma unroll
        for (int i = 0; i < 32; ++i) {
            const ulonglong2 v0 = x0[i];
            const ulonglong2 v1 = x1[i];
            const ulonglong2 v2 = x2[i];
            const ulonglong2 v3 = x3[i];
            const ull wA = wv[2 * i], wB = wv[2 * i + 1];
            a0 = fma2(wA, v0.x, a0); a1 = fma2(wA, v1.x, a1);
            a2 = fma2(wA, v2.x, a2); a3 = fma2(wA, v3.x, a3);
            a0 = fma2(wB, v0.y, a0); a1 = fma2(wB, v1.y, a1);
            a2 = fma2(wB, v2.y, a2); a3 = fma2(wB, v3.y, a3);
        }
        // pair-sum within lane, then cross-lane pair reduce via shfl.xor(1)
        float2 u;
        u = unpack2(a0); float r0 = u.x + u.y;
        u = unpack2(a1); float r1 = u.x + u.y;
        u = unpack2(a2); float r2 = u.x + u.y;
        u = unpack2(a3); float r3 = u.x + u.y;
        const unsigned FULL = 0xffffffffu;
        const float s0 = r0 + __shfl_xor_sync(FULL, r0, 1);
        const float s1 = r1 + __shfl_xor_sync(FULL, r1, 1);
        const float s2 = r2 + __shfl_xor_sync(FULL, r2, 1);
        const float s3 = r3 + __shfl_xor_sync(FULL, r3, 1);

        // ---- update the 2 owned streams (h_prev in registers) ----
        const float zA = (kh ? s2 : s0) + biasr;
        const float zB = (kh ? s3 : s1) + biasr;
        const float thA = ftanh(zA);
        const float thB = ftanh(zB);
        hc0 = fmaf(gc0, hc0 - thA, thA);    // g*h + (1-g)*tanh
        hc1 = fmaf(gc1, hc1 - thB, thB);
        gc0 = gn0; gc1 = gn1;

        // exchange h pairs: each lane gets partner's 2 values -> has all 4
        const float ho0 = __shfl_xor_sync(FULL, hc0, 1);  // partner b: 2(kh^1)
        const float ho1 = __shfl_xor_sync(FULL, hc1, 1);

        if (not_last) {
            const int base = q * PST + row_off;
            const int ob0 = 2 * (kh ^ 1);     // partner's batch pair
            if (!is_waiter) {
                // local storer (kh == rank): 4x STS into local buffer q
                hsh[base + b0 * BST]        = hc0;
                hsh[base + (b0 + 1) * BST]  = hc1;
                hsh[base + ob0 * BST]       = ho0;
                hsh[base + (ob0 + 1) * BST] = ho1;
            } else {
                // peer storer (kh == rank^1, waited): 4x st.cluster
                const uint32_t ra = hr + (uint32_t)base * 4u;
                asm volatile("st.shared::cluster.f32 [%0], %1;"
                             :: "r"(ra + (uint32_t)(b0 * BST) * 4u),
                                "f"(hc0) : "memory");
                asm volatile("st.shared::cluster.f32 [%0], %1;"
                             :: "r"(ra + (uint32_t)((b0 + 1) * BST) * 4u),
                                "f"(hc1) : "memory");
                asm volatile("st.shared::cluster.f32 [%0], %1;"
                             :: "r"(ra + (uint32_t)(ob0 * BST) * 4u),
                                "f"(ho0) : "memory");
                asm volatile("st.shared::cluster.f32 [%0], %1;"
                             :: "r"(ra + (uint32_t)((ob0 + 1) * BST) * 4u),
                                "f"(ho1) : "memory");
            }
            // warp-aggregated remote arrive (orders the 16 peer-store lanes)
            __syncwarp();
            if (arr_lane) {
                asm volatile(
                    "mbarrier.arrive.release.cluster.shared::cluster.b64 _, [%0];"
                    :: "r"(br0 + (uint32_t)q * 8u) : "memory");
            }
        }

        // global out stores (gate nothing)
        const size_t ot = (size_t)t * HH;
        po0[ot] = hc0;
        po1[ot] = hc1;

        // end-of-step local barrier: orders local STS/reads across warps
        __syncthreads();
    }

    // Trailing cluster sync: no CTA exits while peer DSMEM traffic may be
    // in flight toward it.
    asm volatile("barrier.cluster.arrive.aligned;" ::: "memory");
    asm volatile("barrier.cluster.wait.aligned;"   ::: "memory");
}

// ---------------------------------------------------------------------------
extern "C" void kernel_launch(void* const* d_in, const int* in_sizes, int n_in,
                              void* d_out, int out_size)
{
    const float* x   = (const float*)d_in[0];  // [B,T,E]
    const float* Wxw = (const float*)d_in[1];  // [H,E]
    const float* Wxb = (const float*)d_in[2];  // [H]
    const float* Whw = (const float*)d_in[3];  // [H,H]
    const float* Whb = (const float*)d_in[4];  // [H]
    float* out = (float*)d_out;                // [B,T,H]

    dim3 g1(BSZ * TT / 128, HH / 128);
    gates_kernel<<<g1, 256>>>(x, Wxw, Wxb, out);

    mgu_scan<<<(BSZ / NB) * 2, 256>>>(Whw, Whb, out);
}

// round 12
// speedup vs baseline: 1.3195x; 1.3195x over previous
#include <cuda_runtime.h>
#include <cstdint>
#include <cstddef>

// Problem constants
#define BSZ 256      // batch
#define TT  512      // time steps
#define EE  256      // input dim
#define HH  256      // hidden dim
#define NB  4        // batches per cluster

typedef unsigned long long ull;

// ---- packed f32x2 helpers (Blackwell) -------------------------------------
__device__ __forceinline__ ull fma2(ull a, ull b, ull c) {
    ull d;
    asm("fma.rn.f32x2 %0, %1, %2, %3;" : "=l"(d) : "l"(a), "l"(b), "l"(c));
    return d;
}
__device__ __forceinline__ ull splat2(float x) {
    ull d;
    asm("mov.b64 %0, {%1, %1};" : "=l"(d) : "f"(x));
    return d;
}
__device__ __forceinline__ float2 unpack2(ull a) {
    float2 r;
    asm("mov.b64 {%0, %1}, %2;" : "=f"(r.x), "=f"(r.y) : "l"(a));
    return r;
}
__device__ __forceinline__ uint32_t smem_u32(const void* p) {
    uint32_t a;
    asm("{ .reg .u64 t; cvta.to.shared.u64 t, %1; cvt.u32.u64 %0, t; }"
        : "=r"(a) : "l"(p));
    return a;
}

// ---- one-MUFU transcendentals ---------------------------------------------
// 1/d for d in [1,2], NO MUFU. Seed r0 = 24/17 - 8/17*d (|eps| <= 1/17 on
// [1,2]; R11's 48/17 - 32/17*d was the [0.5,1] seed -> diverged -> NaN).
// Two Newton steps: eps^4 ~ 1.2e-5.
__device__ __forceinline__ float rcp_1to2(float d) {
    float r = fmaf(d, -0.47058824f, 1.4117647f);  // 24/17 - 8/17*d
    r = r * fmaf(-d, r, 2.0f);                    // NR1: err ~3.5e-3
    r = r * fmaf(-d, r, 2.0f);                    // NR2: err ~1.2e-5
    return r;
}
// tanh with ONE MUFU (EX2): t = sign(z)*(1-e)/(1+e), e = exp(-2|z|) in (0,1]
__device__ __forceinline__ float ftanh(float z) {
    const float az = fabsf(z);
    const float e = __expf(-2.0f * az);           // 1 MUFU
    const float r = rcp_1to2(1.0f + e);
    const float t = (1.0f - e) * r;
    return copysignf(t, z);
}
// sigmoid with ONE MUFU: e = exp(-|z|); z>=0 -> 1/(1+e), z<0 -> e/(1+e)
__device__ __forceinline__ float fsigmoid(float z) {
    const float az = fabsf(z);
    const float e = __expf(-az);                  // 1 MUFU
    const float r = rcp_1to2(1.0f + e);
    return (z >= 0.0f) ? r : e * r;
}

// ---------------------------------------------------------------------------
// Phase 1: gates = sigmoid(X @ Wx^T + b)  via packed-f32x2 SGEMM.
// (R5 kernel; sigmoid switched to one-MUFU version)
// ---------------------------------------------------------------------------
__global__ __launch_bounds__(256, 2) void gates_kernel(
    const float* __restrict__ X, const float* __restrict__ W,
    const float* __restrict__ bias, float* __restrict__ G)
{
    __shared__ __align__(16) float As[16][128];
    __shared__ __align__(16) float Ws[16][128];

    const int tid = threadIdx.x;
    const int bm = blockIdx.x * 128;
    const int bn = blockIdx.y * 128;
    const int tx = tid & 15;
    const int ty = tid >> 4;
    const int lr = tid >> 2;
    const int lc = (tid & 3) << 2;

    ull acc[8][4];
#pragma unroll
    for (int i = 0; i < 8; ++i)
#pragma unroll
        for (int jj = 0; jj < 4; ++jj) acc[i][jj] = 0ull;

    const float* Xp0 = X + (size_t)(bm + lr) * EE + lc;
    const float* Xp1 = X + (size_t)(bm + lr + 64) * EE + lc;
    const float* Wp0 = W + (size_t)(bn + lr) * EE + lc;
    const float* Wp1 = W + (size_t)(bn + lr + 64) * EE + lc;

    float4 pa0 = *(const float4*)(Xp0);
    float4 pa1 = *(const float4*)(Xp1);
    float4 pw0 = *(const float4*)(Wp0);
    float4 pw1 = *(const float4*)(Wp1);

#pragma unroll 1
    for (int k0 = 0; k0 < EE; k0 += 16) {
        __syncthreads();
        As[lc + 0][lr] = pa0.x; As[lc + 1][lr] = pa0.y;
        As[lc + 2][lr] = pa0.z; As[lc + 3][lr] = pa0.w;
        As[lc + 0][lr + 64] = pa1.x; As[lc + 1][lr + 64] = pa1.y;
        As[lc + 2][lr + 64] = pa1.z; As[lc + 3][lr + 64] = pa1.w;
        Ws[lc + 0][lr] = pw0.x; Ws[lc + 1][lr] = pw0.y;
        Ws[lc + 2][lr] = pw0.z; Ws[lc + 3][lr] = pw0.w;
        Ws[lc + 0][lr + 64] = pw1.x; Ws[lc + 1][lr + 64] = pw1.y;
        Ws[lc + 2][lr + 64] = pw1.z; Ws[lc + 3][lr + 64] = pw1.w;
        __syncthreads();

        if (k0 + 16 < EE) {
            pa0 = *(const float4*)(Xp0 + k0 + 16);
            pa1 = *(const float4*)(Xp1 + k0 + 16);
            pw0 = *(const float4*)(Wp0 + k0 + 16);
            pw1 = *(const float4*)(Wp1 + k0 + 16);
        }

#pragma unroll
        for (int k = 0; k < 16; ++k) {
            float a[8];
            *(float4*)&a[0] = *(const float4*)&As[k][ty * 8];
            *(float4*)&a[4] = *(const float4*)&As[k][ty * 8 + 4];
            ulonglong2 u0 = *(const ulonglong2*)&Ws[k][tx * 8];
            ulonglong2 u1 = *(const ulonglong2*)&Ws[k][tx * 8 + 4];
            const ull b0 = u0.x, b1 = u0.y, b2 = u1.x, b3 = u1.y;
#pragma unroll
            for (int i = 0; i < 8; ++i) {
                const ull s = splat2(a[i]);
                acc[i][0] = fma2(s, b0, acc[i][0]);
                acc[i][1] = fma2(s, b1, acc[i][1]);
                acc[i][2] = fma2(s, b2, acc[i][2]);
                acc[i][3] = fma2(s, b3, acc[i][3]);
            }
        }
    }

    float bb[8];
#pragma unroll
    for (int jj = 0; jj < 8; ++jj) bb[jj] = bias[bn + tx * 8 + jj];

#pragma unroll
    for (int i = 0; i < 8; ++i) {
        const size_t m = bm + ty * 8 + i;
        float v[8];
#pragma unroll
        for (int jj = 0; jj < 4; ++jj) {
            float2 z = unpack2(acc[i][jj]);
            v[2 * jj]     = fsigmoid(z.x + bb[2 * jj]);
            v[2 * jj + 1] = fsigmoid(z.y + bb[2 * jj + 1]);
        }
        float4 o0 = {v[0], v[1], v[2], v[3]};
        float4 o1 = {v[4], v[5], v[6], v[7]};
        *(float4*)(G + m * HH + bn + tx * 8)     = o0;
        *(float4*)(G + m * HH + bn + tx * 8 + 4) = o1;
    }
}

// ---------------------------------------------------------------------------
// Phase 2: MGU recurrence. EXACT Round-5 champion skeleton (894us scan):
//   Cluster(2) x 64, NB=4, 512 steps; 256 threads: j2 = tid&63 -> rows
//   {jg0, jg1=jg0+64}; kq = tid>>6 -> K-quarter (warp-granular roles).
//   W in regs (2 rows x 64 k); remote-quarter warps wait a count-2 mbarrier;
//   matvec -> psum[e][j2][kq] -> syncthreads -> assigned reduce+update
//   (thread (j2,kq) owns e in {2kq, 2kq+1}) -> own 3-way stores ->
//   syncthreads -> tid0 arrives local + remote mbarriers.
//   ONLY change vs R5: ftanh is the one-MUFU version with the CORRECT
//   [1,2] reciprocal seed (MUFU floor 2048 -> 1024 cyc/step).
// ---------------------------------------------------------------------------
__global__ void __cluster_dims__(2, 1, 1) __launch_bounds__(256, 1)
mgu_scan(const float* __restrict__ Whw, const float* __restrict__ Whb,
         float* out)
{
    __shared__ __align__(16) float hsh[2][NB][HH];      // 8 KB ping-pong h
    __shared__ __align__(16) float psum[8 * 64 * 4];    // 8 KB [e][j2][kq]
    __shared__ __align__(8)  ull  bars[2];

    const int tid = threadIdx.x;
    const int j2 = tid & 63;
    const int kq = tid >> 6;
    uint32_t rank;
    asm("mov.u32 %0, %%cluster_ctarank;" : "=r"(rank));
    const int jg0 = (int)rank * 128 + j2;
    const int jg1 = jg0 + 64;
    const int bbase = (blockIdx.x >> 1) * NB;
    // K-quarter [kq*64..) holds h-entries produced by CTA (kq>>1)
    const bool remote_k = ((uint32_t)(kq >> 1) != rank);

    // --- W rows (2 j, this K quarter) into 64 packed registers ---
    ull wv0[32], wv1[32];
    {
        const ulonglong2* wp0 =
            (const ulonglong2*)(Whw + (size_t)jg0 * HH + kq * 64);
        const ulonglong2* wp1 =
            (const ulonglong2*)(Whw + (size_t)jg1 * HH + kq * 64);
#pragma unroll
        for (int i = 0; i < 16; ++i) {
            ulonglong2 a = wp0[i], b = wp1[i];
            wv0[2 * i] = a.x; wv0[2 * i + 1] = a.y;
            wv1[2 * i] = b.x; wv1[2 * i + 1] = b.y;
        }
    }

    for (int i = tid; i < 2 * NB * HH; i += 256)
        ((float*)hsh)[i] = 0.0f;

    if (tid == 0) {
        asm volatile("mbarrier.init.shared.b64 [%0], 2;"
                     :: "r"(smem_u32(&bars[0])) : "memory");
        asm volatile("mbarrier.init.shared.b64 [%0], 2;"
                     :: "r"(smem_u32(&bars[1])) : "memory");
    }

    // ---- assigned update identity: this thread owns e0=2kq, e0+1 ----
    // e = rowhalf*4 + b  (rowhalf: 0 -> jg0, 1 -> jg1)
    const int e0 = 2 * kq;
    const int rowhalf = kq >> 1;
    const int jrow = rowhalf ? jg1 : jg0;
    const int b0 = e0 & 3;           // batches b0, b0+1
    const float biasr = Whb[jrow];

    // out pointers for the 2 owned (batch,row) streams
    float* po0 = out + (size_t)(bbase + b0)     * TT * HH + jrow;
    float* po1 = out + (size_t)(bbase + b0 + 1) * TT * HH + jrow;

    // gates for t=0
    float gc0 = po0[0], gc1 = po1[0];

    // cluster addresses
    const uint32_t hl = smem_u32(hsh);
    const uint32_t bl0 = smem_u32(&bars[0]);
    uint32_t hr, br0;
    asm("mapa.shared::cluster.u32 %0, %1, %2;"
        : "=r"(hr) : "r"(hl), "r"(rank ^ 1u));
    asm("mapa.shared::cluster.u32 %0, %1, %2;"
        : "=r"(br0) : "r"(bl0), "r"(rank ^ 1u));

    __syncthreads();
    // one-time: both CTAs' smem init + mbarrier init visible cluster-wide
    asm volatile("barrier.cluster.arrive.aligned;" ::: "memory");
    asm volatile("barrier.cluster.wait.aligned;"   ::: "memory");

    uint32_t ph0 = 0, ph1 = 0;

#pragma unroll 1
    for (int t = 0; t < TT; ++t) {
        const int p = t & 1;
        const int q = p ^ 1;
        const bool not_last = (t + 1 < TT);

        // prefetch gates for t+1 (issued before any waiting)
        float gn0 = 0.f, gn1 = 0.f;
        if (not_last) {
            const size_t o = (size_t)(t + 1) * HH;
            gn0 = po0[o]; gn1 = po1[o];
        }

        // remote-K threads wait for peer's h(t) delivery into buffer p
        if (t > 0 && remote_k) {
            const uint32_t mb = bl0 + (uint32_t)p * 8u;
            const uint32_t par = p ? ph1 : ph0;
            uint32_t done;
            do {
                asm volatile(
                    "{\n\t.reg .pred P;\n\t"
                    "mbarrier.try_wait.parity.acquire.cluster.shared::cta.b64 "
                    "P, [%1], %2, 0x989680;\n\t"
                    "selp.b32 %0, 1, 0, P;\n\t}"
                    : "=r"(done) : "r"(mb), "r"(par) : "memory");
            } while (!done);
        }
        if (t > 0) { if (p) ph1 ^= 1; else ph0 ^= 1; }

        // ---- matvec over this thread's K-quarter (ratio 4 fma2 : 1 LDS) ----
        const float* hb = &hsh[p][0][kq * 64];
        ull a00 = 0, a01 = 0, a02 = 0, a03 = 0;   // row jg0, batches 0..3
        ull a10 = 0, a11 = 0, a12 = 0, a13 = 0;   // row jg1
#pragma unroll
        for (int i = 0; i < 16; ++i) {
            const ulonglong2 v0 = ((const ulonglong2*)(hb          ))[i];
            const ulonglong2 v1 = ((const ulonglong2*)(hb + HH     ))[i];
            const ulonglong2 v2 = ((const ulonglong2*)(hb + 2 * HH))[i];
            const ulonglong2 v3 = ((const ulonglong2*)(hb + 3 * HH))[i];
            const ull wA0 = wv0[2 * i], wB0 = wv0[2 * i + 1];
            const ull wA1 = wv1[2 * i], wB1 = wv1[2 * i + 1];
            a00 = fma2(wA0, v0.x, a00); a01 = fma2(wA0, v1.x, a01);
            a02 = fma2(wA0, v2.x, a02); a03 = fma2(wA0, v3.x, a03);
            a10 = fma2(wA1, v0.x, a10); a11 = fma2(wA1, v1.x, a11);
            a12 = fma2(wA1, v2.x, a12); a13 = fma2(wA1, v3.x, a13);
            a00 = fma2(wB0, v0.y, a00); a01 = fma2(wB0, v1.y, a01);
            a02 = fma2(wB0, v2.y, a02); a03 = fma2(wB0, v3.y, a03);
            a10 = fma2(wB1, v0.y, a10); a11 = fma2(wB1, v1.y, a11);
            a12 = fma2(wB1, v2.y, a12); a13 = fma2(wB1, v3.y, a13);
        }
        // pair-sum + publish partials: psum[e][j2][kq], e = rowhalf*4 + b
        {
            float r[8];
            float2 u;
            u = unpack2(a00); r[0] = u.x + u.y;
            u = unpack2(a01); r[1] = u.x + u.y;
            u = unpack2(a02); r[2] = u.x + u.y;
            u = unpack2(a03); r[3] = u.x + u.y;
            u = unpack2(a10); r[4] = u.x + u.y;
            u = unpack2(a11); r[5] = u.x + u.y;
            u = unpack2(a12); r[6] = u.x + u.y;
            u = unpack2(a13); r[7] = u.x + u.y;
#pragma unroll
            for (int e = 0; e < 8; ++e)
                psum[(e * 64 + j2) * 4 + kq] = r[e];
        }
        __syncthreads();

        // ---- assigned reduce + update (2 values per thread) ----
        const float4 pv0 = *(const float4*)&psum[(e0 * 64 + j2) * 4];
        const float4 pv1 = *(const float4*)&psum[((e0 + 1) * 64 + j2) * 4];
        const float z0 = (pv0.x + pv0.y) + (pv0.z + pv0.w) + biasr;
        const float z1 = (pv1.x + pv1.y) + (pv1.z + pv1.w) + biasr;
        const float th0 = ftanh(z0);
        const float th1 = ftanh(z1);
        const float hp0 = hsh[p][b0][jrow];
        const float hp1 = hsh[p][b0 + 1][jrow];
        const float h0 = fmaf(gc0, hp0 - th0, th0);   // g*h + (1-g)*tanh
        const float h1 = fmaf(gc1, hp1 - th1, th1);
        gc0 = gn0; gc1 = gn1;

        // ---- this thread's 3-way stores for its 2 values ----
        const size_t ot = (size_t)t * HH;
        po0[ot] = h0;
        po1[ot] = h1;
        if (not_last) {
            hsh[q][b0][jrow]     = h0;
            hsh[q][b0 + 1][jrow] = h1;
            const uint32_t ra0 = hr +
                (uint32_t)(((q * NB + b0) * HH + jrow) * 4);
            asm volatile("st.shared::cluster.f32 [%0], %1;"
                         :: "r"(ra0), "f"(h0) : "memory");
            asm volatile("st.shared::cluster.f32 [%0], %1;"
                         :: "r"(ra0 + (uint32_t)(HH * 4)), "f"(h1) : "memory");
        }
        __syncthreads();

        if (tid == 0 && not_last) {  // signal buffer q: local + remote arrive
            const uint32_t off = (uint32_t)q * 8u;
            asm volatile(
                "mbarrier.arrive.release.cluster.shared::cta.b64 _, [%0];"
                :: "r"(bl0 + off) : "memory");
            asm volatile(
                "mbarrier.arrive.release.cluster.shared::cluster.b64 _, [%0];"
                :: "r"(br0 + off) : "memory");
        }
    }

    // Trailing cluster sync: no CTA exits while peer DSMEM traffic may be
    // in flight toward it (exit race = unspecified launch failure).
    asm volatile("barrier.cluster.arrive.aligned;" ::: "memory");
    asm volatile("barrier.cluster.wait.aligned;"   ::: "memory");
}

// ---------------------------------------------------------------------------
extern "C" void kernel_launch(void* const* d_in, const int* in_sizes, int n_in,
                              void* d_out, int out_size)
{
    const float* x   = (const float*)d_in[0];  // [B,T,E]
    const float* Wxw = (const float*)d_in[1];  // [H,E]
    const float* Wxb = (const float*)d_in[2];  // [H]
    const float* Whw = (const float*)d_in[3];  // [H,H]
    const float* Whb = (const float*)d_in[4];  // [H]
    float* out = (float*)d_out;                // [B,T,H]

    dim3 g1(BSZ * TT / 128, HH / 128);
    gates_kernel<<<g1, 256>>>(x, Wxw, Wxb, out);

    mgu_scan<<<(BSZ / NB) * 2, 256>>>(Whw, Whb, out);
}

// round 13
// speedup vs baseline: 1.4542x; 1.1020x over previous
#include <cuda_runtime.h>
#include <cstdint>
#include <cstddef>

// Problem constants
#define BSZ 256      // batch
#define TT  512      // time steps
#define EE  256      // input dim
#define HH  256      // hidden dim
#define NB  4        // batches per cluster

typedef unsigned long long ull;

// ---- packed f32x2 helpers (Blackwell) -------------------------------------
__device__ __forceinline__ ull fma2(ull a, ull b, ull c) {
    ull d;
    asm("fma.rn.f32x2 %0, %1, %2, %3;" : "=l"(d) : "l"(a), "l"(b), "l"(c));
    return d;
}
__device__ __forceinline__ ull splat2(float x) {
    ull d;
    asm("mov.b64 %0, {%1, %1};" : "=l"(d) : "f"(x));
    return d;
}
__device__ __forceinline__ float2 unpack2(ull a) {
    float2 r;
    asm("mov.b64 {%0, %1}, %2;" : "=f"(r.x), "=f"(r.y) : "l"(a));
    return r;
}
__device__ __forceinline__ uint32_t smem_u32(const void* p) {
    uint32_t a;
    asm("{ .reg .u64 t; cvta.to.shared.u64 t, %1; cvt.u32.u64 %0, t; }"
        : "=r"(a) : "l"(p));
    return a;
}

// ---- one-MUFU transcendentals (correct [1,2] reciprocal seed) --------------
__device__ __forceinline__ float rcp_1to2(float d) {
    float r = fmaf(d, -0.47058824f, 1.4117647f);  // 24/17 - 8/17*d
    r = r * fmaf(-d, r, 2.0f);                    // NR1
    r = r * fmaf(-d, r, 2.0f);                    // NR2: err ~1.2e-5
    return r;
}
__device__ __forceinline__ float ftanh(float z) {
    const float az = fabsf(z);
    const float e = __expf(-2.0f * az);           // 1 MUFU
    const float r = rcp_1to2(1.0f + e);
    const float t = (1.0f - e) * r;
    return copysignf(t, z);
}
__device__ __forceinline__ float fsigmoid(float z) {
    const float az = fabsf(z);
    const float e = __expf(-az);                  // 1 MUFU
    const float r = rcp_1to2(1.0f + e);
    return (z >= 0.0f) ? r : e * r;
}

// ---------------------------------------------------------------------------
// Phase 1: gates = sigmoid(X @ Wx^T + b)  via packed-f32x2 SGEMM. (unchanged)
// ---------------------------------------------------------------------------
__global__ __launch_bounds__(256, 2) void gates_kernel(
    const float* __restrict__ X, const float* __restrict__ W,
    const float* __restrict__ bias, float* __restrict__ G)
{
    __shared__ __align__(16) float As[16][128];
    __shared__ __align__(16) float Ws[16][128];

    const int tid = threadIdx.x;
    const int bm = blockIdx.x * 128;
    const int bn = blockIdx.y * 128;
    const int tx = tid & 15;
    const int ty = tid >> 4;
    const int lr = tid >> 2;
    const int lc = (tid & 3) << 2;

    ull acc[8][4];
#pragma unroll
    for (int i = 0; i < 8; ++i)
#pragma unroll
        for (int jj = 0; jj < 4; ++jj) acc[i][jj] = 0ull;

    const float* Xp0 = X + (size_t)(bm + lr) * EE + lc;
    const float* Xp1 = X + (size_t)(bm + lr + 64) * EE + lc;
    const float* Wp0 = W + (size_t)(bn + lr) * EE + lc;
    const float* Wp1 = W + (size_t)(bn + lr + 64) * EE + lc;

    float4 pa0 = *(const float4*)(Xp0);
    float4 pa1 = *(const float4*)(Xp1);
    float4 pw0 = *(const float4*)(Wp0);
    float4 pw1 = *(const float4*)(Wp1);

#pragma unroll 1
    for (int k0 = 0; k0 < EE; k0 += 16) {
        __syncthreads();
        As[lc + 0][lr] = pa0.x; As[lc + 1][lr] = pa0.y;
        As[lc + 2][lr] = pa0.z; As[lc + 3][lr] = pa0.w;
        As[lc + 0][lr + 64] = pa1.x; As[lc + 1][lr + 64] = pa1.y;
        As[lc + 2][lr + 64] = pa1.z; As[lc + 3][lr + 64] = pa1.w;
        Ws[lc + 0][lr] = pw0.x; Ws[lc + 1][lr] = pw0.y;
        Ws[lc + 2][lr] = pw0.z; Ws[lc + 3][lr] = pw0.w;
        Ws[lc + 0][lr + 64] = pw1.x; Ws[lc + 1][lr + 64] = pw1.y;
        Ws[lc + 2][lr + 64] = pw1.z; Ws[lc + 3][lr + 64] = pw1.w;
        __syncthreads();

        if (k0 + 16 < EE) {
            pa0 = *(const float4*)(Xp0 + k0 + 16);
            pa1 = *(const float4*)(Xp1 + k0 + 16);
            pw0 = *(const float4*)(Wp0 + k0 + 16);
            pw1 = *(const float4*)(Wp1 + k0 + 16);
        }

#pragma unroll
        for (int k = 0; k < 16; ++k) {
            float a[8];
            *(float4*)&a[0] = *(const float4*)&As[k][ty * 8];
            *(float4*)&a[4] = *(const float4*)&As[k][ty * 8 + 4];
            ulonglong2 u0 = *(const ulonglong2*)&Ws[k][tx * 8];
            ulonglong2 u1 = *(const ulonglong2*)&Ws[k][tx * 8 + 4];
            const ull b0 = u0.x, b1 = u0.y, b2 = u1.x, b3 = u1.y;
#pragma unroll
            for (int i = 0; i < 8; ++i) {
                const ull s = splat2(a[i]);
                acc[i][0] = fma2(s, b0, acc[i][0]);
                acc[i][1] = fma2(s, b1, acc[i][1]);
                acc[i][2] = fma2(s, b2, acc[i][2]);
                acc[i][3] = fma2(s, b3, acc[i][3]);
            }
        }
    }

    float bb[8];
#pragma unroll
    for (int jj = 0; jj < 8; ++jj) bb[jj] = bias[bn + tx * 8 + jj];

#pragma unroll
    for (int i = 0; i < 8; ++i) {
        const size_t m = bm + ty * 8 + i;
        float v[8];
#pragma unroll
        for (int jj = 0; jj < 4; ++jj) {
            float2 z = unpack2(acc[i][jj]);
            v[2 * jj]     = fsigmoid(z.x + bb[2 * jj]);
            v[2 * jj + 1] = fsigmoid(z.y + bb[2 * jj + 1]);
        }
        float4 o0 = {v[0], v[1], v[2], v[3]};
        float4 o1 = {v[4], v[5], v[6], v[7]};
        *(float4*)(G + m * HH + bn + tx * 8)     = o0;
        *(float4*)(G + m * HH + bn + tx * 8 + 4) = o1;
    }
}

// ---------------------------------------------------------------------------
// Phase 2: MGU recurrence — R5 skeleton + conflict-free psum + early arrives.
//   Cluster(2) x 64, NB=4, 512 steps; 256 threads: j2 = tid&63 -> rows
//   {jg0, jg1=jg0+64}; kq = tid>>6 -> K-quarter (warp-granular wait roles).
//   Changes vs R12:
//   1. psum layout [e][kq][j2]: stores AND reduce loads are 1-wavefront
//      coalesced (was 4-way / 16-way conflicted: ~500 cyc/step of crossbar).
//   2. mb count 2 -> 8: each warp posts arrive.release on the PEER's mb[q]
//      right after its own st.cluster + __syncwarp (mid-step, flight overlaps
//      the tail). tid0 handshake + local arrive removed; BAR2 still orders
//      the local h-half for next step's local readers.
//   Cross-CTA WAR: my h-stores at t are after BAR1(t), which syncs with my
//   remote-k warps' wait on peer's step-(t-1) arrivals (posted after peer's
//   reads of buffer q). Lap-safe: peer's t+2 arrivals transitively require
//   my t+1 wait, which consumed the t-phase.
// ---------------------------------------------------------------------------
__global__ void __cluster_dims__(2, 1, 1) __launch_bounds__(256, 1)
mgu_scan(const float* __restrict__ Whw, const float* __restrict__ Whb,
         float* out)
{
    __shared__ __align__(16) float hsh[2][NB][HH];      // 8 KB ping-pong h
    __shared__ __align__(16) float psum[8][4][64];      // 8 KB [e][kq][j2]
    __shared__ __align__(8)  ull  bars[2];

    const int tid = threadIdx.x;
    const int j2 = tid & 63;
    const int kq = tid >> 6;
    uint32_t rank;
    asm("mov.u32 %0, %%cluster_ctarank;" : "=r"(rank));
    const int jg0 = (int)rank * 128 + j2;
    const int jg1 = jg0 + 64;
    const int bbase = (blockIdx.x >> 1) * NB;
    // K-quarter [kq*64..) holds h-entries produced by CTA (kq>>1)
    const bool remote_k = ((uint32_t)(kq >> 1) != rank);

    // --- W rows (2 j, this K quarter) into 64 packed registers ---
    ull wv0[32], wv1[32];
    {
        const ulonglong2* wp0 =
            (const ulonglong2*)(Whw + (size_t)jg0 * HH + kq * 64);
        const ulonglong2* wp1 =
            (const ulonglong2*)(Whw + (size_t)jg1 * HH + kq * 64);
#pragma unroll
        for (int i = 0; i < 16; ++i) {
            ulonglong2 a = wp0[i], b = wp1[i];
            wv0[2 * i] = a.x; wv0[2 * i + 1] = a.y;
            wv1[2 * i] = b.x; wv1[2 * i + 1] = b.y;
        }
    }

    for (int i = tid; i < 2 * NB * HH; i += 256)
        ((float*)hsh)[i] = 0.0f;

    if (tid == 0) {
        asm volatile("mbarrier.init.shared.b64 [%0], 8;"
                     :: "r"(smem_u32(&bars[0])) : "memory");
        asm volatile("mbarrier.init.shared.b64 [%0], 8;"
                     :: "r"(smem_u32(&bars[1])) : "memory");
    }

    // ---- assigned update identity: this thread owns e0=2kq, e0+1 ----
    const int e0 = 2 * kq;
    const int rowhalf = kq >> 1;
    const int jrow = rowhalf ? jg1 : jg0;
    const int b0 = e0 & 3;           // batches b0, b0+1
    const float biasr = Whb[jrow];

    // out pointers for the 2 owned (batch,row) streams
    float* po0 = out + (size_t)(bbase + b0)     * TT * HH + jrow;
    float* po1 = out + (size_t)(bbase + b0 + 1) * TT * HH + jrow;

    // gates for t=0
    float gc0 = po0[0], gc1 = po1[0];

    // cluster addresses
    const uint32_t hl = smem_u32(hsh);
    const uint32_t bl0 = smem_u32(&bars[0]);
    uint32_t hr, br0;
    asm("mapa.shared::cluster.u32 %0, %1, %2;"
        : "=r"(hr) : "r"(hl), "r"(rank ^ 1u));
    asm("mapa.shared::cluster.u32 %0, %1, %2;"
        : "=r"(br0) : "r"(bl0), "r"(rank ^ 1u));

    const bool lane0 = ((tid & 31) == 0);

    __syncthreads();
    // one-time: both CTAs' smem init + mbarrier init visible cluster-wide
    asm volatile("barrier.cluster.arrive.aligned;" ::: "memory");
    asm volatile("barrier.cluster.wait.aligned;"   ::: "memory");

    uint32_t ph0 = 0, ph1 = 0;

#pragma unroll 1
    for (int t = 0; t < TT; ++t) {
        const int p = t & 1;
        const int q = p ^ 1;
        const bool not_last = (t + 1 < TT);

        // prefetch gates for t+1 (issued before any waiting)
        float gn0 = 0.f, gn1 = 0.f;
        if (not_last) {
            const size_t o = (size_t)(t + 1) * HH;
            gn0 = po0[o]; gn1 = po1[o];
        }

        // remote-K warps wait for the peer's 8 warp-arrivals into buffer p
        if (t > 0 && remote_k) {
            const uint32_t mb = bl0 + (uint32_t)p * 8u;
            const uint32_t par = p ? ph1 : ph0;
            uint32_t done;
            do {
                asm volatile(
                    "{\n\t.reg .pred P;\n\t"
                    "mbarrier.try_wait.parity.acquire.cluster.shared::cta.b64 "
                    "P, [%1], %2, 0x989680;\n\t"
                    "selp.b32 %0, 1, 0, P;\n\t}"
                    : "=r"(done) : "r"(mb), "r"(par) : "memory");
            } while (!done);
        }
        if (t > 0) { if (p) ph1 ^= 1; else ph0 ^= 1; }

        // ---- matvec over this thread's K-quarter (ratio 4 fma2 : 1 LDS) ----
        const float* hb = &hsh[p][0][kq * 64];
        ull a00 = 0, a01 = 0, a02 = 0, a03 = 0;   // row jg0, batches 0..3
        ull a10 = 0, a11 = 0, a12 = 0, a13 = 0;   // row jg1
#pragma unroll
        for (int i = 0; i < 16; ++i) {
            const ulonglong2 v0 = ((const ulonglong2*)(hb          ))[i];
            const ulonglong2 v1 = ((const ulonglong2*)(hb + HH     ))[i];
            const ulonglong2 v2 = ((const ulonglong2*)(hb + 2 * HH))[i];
            const ulonglong2 v3 = ((const ulonglong2*)(hb + 3 * HH))[i];
            const ull wA0 = wv0[2 * i], wB0 = wv0[2 * i + 1];
            const ull wA1 = wv1[2 * i], wB1 = wv1[2 * i + 1];
            a00 = fma2(wA0, v0.x, a00); a01 = fma2(wA0, v1.x, a01);
            a02 = fma2(wA0, v2.x, a02); a03 = fma2(wA0, v3.x, a03);
            a10 = fma2(wA1, v0.x, a10); a11 = fma2(wA1, v1.x, a11);
            a12 = fma2(wA1, v2.x, a12); a13 = fma2(wA1, v3.x, a13);
            a00 = fma2(wB0, v0.y, a00); a01 = fma2(wB0, v1.y, a01);
            a02 = fma2(wB0, v2.y, a02); a03 = fma2(wB0, v3.y, a03);
            a10 = fma2(wB1, v0.y, a10); a11 = fma2(wB1, v1.y, a11);
            a12 = fma2(wB1, v2.y, a12); a13 = fma2(wB1, v3.y, a13);
        }
        // pair-sum + publish partials: psum[e][kq][j2] (coalesced stores)
        {
            float r[8];
            float2 u;
            u = unpack2(a00); r[0] = u.x + u.y;
            u = unpack2(a01); r[1] = u.x + u.y;
            u = unpack2(a02); r[2] = u.x + u.y;
            u = unpack2(a03); r[3] = u.x + u.y;
            u = unpack2(a10); r[4] = u.x + u.y;
            u = unpack2(a11); r[5] = u.x + u.y;
            u = unpack2(a12); r[6] = u.x + u.y;
            u = unpack2(a13); r[7] = u.x + u.y;
#pragma unroll
            for (int e = 0; e < 8; ++e)
                psum[e][kq][j2] = r[e];
        }
        __syncthreads();   // BAR1: psum visible; also propagates mb-wait

        // ---- assigned reduce + update (coalesced scalar LDS) ----
        const float z0 = ((psum[e0][0][j2]     + psum[e0][1][j2]) +
                          (psum[e0][2][j2]     + psum[e0][3][j2])) + biasr;
        const float z1 = ((psum[e0 + 1][0][j2] + psum[e0 + 1][1][j2]) +
                          (psum[e0 + 1][2][j2] + psum[e0 + 1][3][j2])) + biasr;
        const float th0 = ftanh(z0);
        const float th1 = ftanh(z1);
        const float hp0 = hsh[p][b0][jrow];
        const float hp1 = hsh[p][b0 + 1][jrow];
        const float h0 = fmaf(gc0, hp0 - th0, th0);   // g*h + (1-g)*tanh
        const float h1 = fmaf(gc1, hp1 - th1, th1);
        gc0 = gn0; gc1 = gn1;

        if (not_last) {
            // peer DSMEM stores first (longest flight), then local, then the
            // warp-aggregated early remote arrive.
            const uint32_t ra0 = hr +
                (uint32_t)(((q * NB + b0) * HH + jrow) * 4);
            asm volatile("st.shared::cluster.f32 [%0], %1;"
                         :: "r"(ra0), "f"(h0) : "memory");
            asm volatile("st.shared::cluster.f32 [%0], %1;"
                         :: "r"(ra0 + (uint32_t)(HH * 4)), "f"(h1) : "memory");
            hsh[q][b0][jrow]     = h0;
            hsh[q][b0 + 1][jrow] = h1;
            __syncwarp();
            if (lane0) {
                asm volatile(
                    "mbarrier.arrive.release.cluster.shared::cluster.b64 _, [%0];"
                    :: "r"(br0 + (uint32_t)q * 8u) : "memory");
            }
        }

        // global out stores (gate nothing)
        const size_t ot = (size_t)t * HH;
        po0[ot] = h0;
        po1[ot] = h1;

        __syncthreads();   // BAR2: local h-half ordered for next step
    }

    // Trailing cluster sync: no CTA exits while peer DSMEM traffic may be
    // in flight toward it.
    asm volatile("barrier.cluster.arrive.aligned;" ::: "memory");
    asm volatile("barrier.cluster.wait.aligned;"   ::: "memory");
}

// ---------------------------------------------------------------------------
extern "C" void kernel_launch(void* const* d_in, const int* in_sizes, int n_in,
                              void* d_out, int out_size)
{
    const float* x   = (const float*)d_in[0];  // [B,T,E]
    const float* Wxw = (const float*)d_in[1];  // [H,E]
    const float* Wxb = (const float*)d_in[2];  // [H]
    const float* Whw = (const float*)d_in[3];  // [H,H]
    const float* Whb = (const float*)d_in[4];  // [H]
    float* out = (float*)d_out;                // [B,T,H]

    dim3 g1(BSZ * TT / 128, HH / 128);
    gates_kernel<<<g1, 256>>>(x, Wxw, Wxb, out);

    mgu_scan<<<(BSZ / NB) * 2, 256>>>(Whw, Whb, out);
}